// round 13
// baseline (speedup 1.0000x reference)
#include <cuda_runtime.h>
#include <math.h>
#include <stdint.h>

#define NB   64
#define CIN  256
#define COUT 256
#define HH   56
#define HW   (HH * HH)         // 3136
#define NWORDS 8
#define TAPS 9
#define KW   (TAPS * NWORDS)   // 72 k-words
#define EPSC 1e-5
#define NSLICE 8

__device__ float        g_scale[CIN];
__device__ float        g_shift[CIN];
__device__ double       g_part[CIN * NSLICE * 2];
__device__ unsigned int g_xbits[(size_t)NB * HW * NWORDS];     // [n][pix][word]
__device__ unsigned int g_wkt[KW * COUT];                      // k-major: [k][co]

// ---------------------------------------------------------------------------
// 1) BN stats stage 1: fp32 per-thread partials, double reduction.
// ---------------------------------------------------------------------------
__global__ void bn_stats1_kernel(const float* __restrict__ x) {
    const int c = blockIdx.x, slice = blockIdx.y, nper = NB / NSLICE;
    float fs = 0.f, fs2 = 0.f;
    for (int n = slice * nper; n < (slice + 1) * nper; ++n) {
        const float4* p = (const float4*)(x + ((size_t)n * CIN + c) * HW);
        for (int i = threadIdx.x; i < HW / 4; i += blockDim.x) {
            float4 v = p[i];
            fs  += v.x + v.y + v.z + v.w;
            fs2 += v.x * v.x + v.y * v.y + v.z * v.z + v.w * v.w;
        }
    }
    double s = (double)fs, s2 = (double)fs2;
    __shared__ double ws[32], ws2[32];
    #pragma unroll
    for (int o = 16; o > 0; o >>= 1) {
        s  += __shfl_down_sync(0xffffffffu, s,  o);
        s2 += __shfl_down_sync(0xffffffffu, s2, o);
    }
    const int warp = threadIdx.x >> 5, lane = threadIdx.x & 31;
    if (lane == 0) { ws[warp] = s; ws2[warp] = s2; }
    __syncthreads();
    if (warp == 0) {
        const int nw = blockDim.x >> 5;
        s  = (lane < nw) ? ws[lane]  : 0.0;
        s2 = (lane < nw) ? ws2[lane] : 0.0;
        #pragma unroll
        for (int o = 16; o > 0; o >>= 1) {
            s  += __shfl_down_sync(0xffffffffu, s,  o);
            s2 += __shfl_down_sync(0xffffffffu, s2, o);
        }
        if (lane == 0) {
            g_part[(c * NSLICE + slice) * 2 + 0] = s;
            g_part[(c * NSLICE + slice) * 2 + 1] = s2;
        }
    }
}

// ---------------------------------------------------------------------------
// 2) FUSED: weight bit-pack (k-major) AND bn stage-2 fold (block 0).
// ---------------------------------------------------------------------------
__global__ void packw_bn2_kernel(const float* __restrict__ w,
                                 const float* __restrict__ gamma,
                                 const float* __restrict__ beta) {
    if (blockIdx.x == 0 && threadIdx.x < CIN) {
        const int c = threadIdx.x;
        double s = 0.0, s2 = 0.0;
        #pragma unroll
        for (int k = 0; k < NSLICE; ++k) {
            s  += g_part[(c * NSLICE + k) * 2 + 0];
            s2 += g_part[(c * NSLICE + k) * 2 + 1];
        }
        const double Nt = (double)NB * (double)HW;
        double mean = s / Nt;
        double var  = s2 / Nt - mean * mean;
        float sc = (float)(1.0 / sqrt(var + EPSC)) * gamma[c];
        g_scale[c] = sc;
        g_shift[c] = beta[c] - (float)mean * sc;
    }
    const int idx = blockIdx.x * blockDim.x + threadIdx.x;   // COUT*72
    if (idx >= COUT * KW) return;
    const int word = idx & 7;
    const int tap  = (idx >> 3) % TAPS;
    const int co   = idx / KW;
    const float* p = w + ((size_t)co * CIN + word * 32) * TAPS + tap;
    unsigned int bits = 0;
    #pragma unroll
    for (int j = 0; j < 32; ++j)
        if (p[(size_t)j * TAPS] > 0.0f) bits |= (1u << j);
    g_wkt[(tap * NWORDS + word) * COUT + co] = bits;
}

// ---------------------------------------------------------------------------
// 3) Binarize + bit-pack activations.
// ---------------------------------------------------------------------------
__global__ void pack_x_kernel(const float* __restrict__ x) {
    const int idx = blockIdx.x * blockDim.x + threadIdx.x;
    if (idx >= NB * NWORDS * HW) return;
    const int s    = idx % HW;
    const int t    = idx / HW;
    const int word = t & 7;
    const int n    = t >> 3;
    const int cbase = word * 32;
    const float* p = x + ((size_t)(n * CIN + cbase)) * HW + s;
    unsigned int bits = 0;
    #pragma unroll
    for (int j = 0; j < 32; ++j) {
        float xh = fmaf(p[(size_t)j * HW], g_scale[cbase + j], g_shift[cbase + j]);
        if (xh > 0.0f) bits |= (1u << j);
    }
    g_xbits[((size_t)n * HW + s) * NWORDS + word] = bits;
}

// ---------------------------------------------------------------------------
// 4) GEMM-tiled XNOR-popcount conv.
//    Block: 64 pixels x 64 c_out, 256 threads, thread tile 4x4.
//    Accumulation moved to the FMA pipe via IMAD (mad.lo with runtime 'one').
// ---------------------------------------------------------------------------
#define MPIX 64
#define NCO  64
#define OFF_XS 0
#define OFF_WS (KW * MPIX)
#define OFF_VM (2 * KW * MPIX)
#define OFF_NV (2 * KW * MPIX + TAPS * MPIX)
#define OFF_SB (OFF_NV + MPIX)
#define OFF_ONE (OFF_SB + NCO)
#define SMEM_CONV ((OFF_ONE + 1) * 4)

__global__ void __launch_bounds__(256, 4)
bconv_kernel(const float* __restrict__ bias, float* __restrict__ out) {
    extern __shared__ unsigned int sm[];
    unsigned int* sxs = sm + OFF_XS;
    unsigned int* sws = sm + OFF_WS;
    unsigned int* svm = sm + OFF_VM;
    int*          snv = (int*)(sm + OFF_NV);
    float*        sb  = (float*)(sm + OFF_SB);

    const int tid = threadIdx.x;
    const int p0  = blockIdx.x * MPIX;
    const int co0 = blockIdx.y * NCO;
    const int n   = blockIdx.z;

    if (tid == 0) ((int*)sm)[OFF_ONE] = 1;

    // fill weights (k-major sub-columns), vectorized
    {
        const uint4* src = (const uint4*)(g_wkt);
        uint4* dst = (uint4*)sws;
        for (int i = tid; i < KW * (NCO / 4); i += 256) {
            const int k = i >> 4, q = i & 15;
            dst[k * 16 + q] = src[(k * COUT + co0) / 4 + q];
        }
    }
    // fill x im2col + validity masks
    const unsigned int* xb = g_xbits + (size_t)n * HW * NWORDS;
    for (int i = tid; i < KW * MPIX; i += 256) {
        const int k = i >> 6, j = i & 63;
        const int tap = k >> 3, word = k & 7;
        const int dh = tap / 3 - 1, dw = tap % 3 - 1;
        const int p = p0 + j;
        const int h = p / HH, w = p % HH;
        const int hh = h + dh, ww = w + dw;
        const bool valid = (hh >= 0) & (hh < HH) & (ww >= 0) & (ww < HH);
        sxs[i] = valid ? xb[((size_t)hh * HH + ww) * NWORDS + word] : 0u;
        if (word == 0) svm[tap * MPIX + j] = valid ? 0xffffffffu : 0u;
    }
    // nvalid per pixel + bias
    if (tid < MPIX) {
        const int p = p0 + tid;
        const int h = p / HH, w = p % HH;
        int nv = 0;
        #pragma unroll
        for (int tap = 0; tap < TAPS; ++tap) {
            const int hh = h + tap / 3 - 1, ww = w + tap % 3 - 1;
            nv += ((hh >= 0) & (hh < HH) & (ww >= 0) & (ww < HH)) ? 1 : 0;
        }
        snv[tid] = nv;
        sb[tid]  = bias[co0 + tid];
    }
    __syncthreads();

    const int one = ((int*)sm)[OFF_ONE];   // runtime 1: forces IMAD (fma pipe)
    const int pj = (tid & 15) * 4;
    const int cj = (tid >> 4) * 4;

    int acc[4][4];
    #pragma unroll
    for (int i = 0; i < 4; ++i)
        #pragma unroll
        for (int j = 0; j < 4; ++j) acc[i][j] = 0;

    #pragma unroll 1
    for (int tap = 0; tap < TAPS; ++tap) {
        const uint4 vm = *(const uint4*)(svm + tap * MPIX + pj);
        unsigned int va[4] = {vm.x, vm.y, vm.z, vm.w};
        #pragma unroll
        for (int wd = 0; wd < NWORDS; ++wd) {
            const int k = tap * NWORDS + wd;
            const uint4 xv = *(const uint4*)(sxs + k * MPIX + pj);
            const uint4 wv = *(const uint4*)(sws + k * NCO + cj);
            unsigned int xa[4] = {xv.x, xv.y, xv.z, xv.w};
            unsigned int wa[4] = {wv.x, wv.y, wv.z, wv.w};
            #pragma unroll
            for (int i = 0; i < 4; ++i) {
                #pragma unroll
                for (int j = 0; j < 4; ++j) {
                    const int p = __popc((xa[i] ^ wa[j]) & va[i]);
                    asm("mad.lo.s32 %0, %1, %2, %0;"
                        : "+r"(acc[i][j]) : "r"(p), "r"(one));
                }
            }
        }
    }

    // epilogue
    #pragma unroll
    for (int i = 0; i < 4; ++i) {
        const int p = p0 + pj + i;
        const int base = CIN * snv[pj + i];
        float* op = out + (size_t)n * COUT * HW + p;
        #pragma unroll
        for (int j = 0; j < 4; ++j) {
            const int co = cj + j;
            const float y = (float)(base - 2 * acc[i][j]) + sb[co];
            op[(size_t)(co0 + co) * HW] = fmaxf(y, 0.0f);
        }
    }
}

// ---------------------------------------------------------------------------
extern "C" void kernel_launch(void* const* d_in, const int* in_sizes, int n_in,
                              void* d_out, int out_size) {
    const float* x     = (const float*)d_in[0];
    const float* gamma = (const float*)d_in[1];
    const float* beta  = (const float*)d_in[2];
    const float* w     = (const float*)d_in[3];
    const float* b     = (const float*)d_in[4];
    float* out = (float*)d_out;

    dim3 sgrid(CIN, NSLICE);
    bn_stats1_kernel<<<sgrid, 256>>>(x);

    packw_bn2_kernel<<<(COUT * KW + 255) / 256, 256>>>(w, gamma, beta);

    const int pxn = NB * NWORDS * HW;
    pack_x_kernel<<<(pxn + 255) / 256, 256>>>(x);

    cudaFuncSetAttribute(bconv_kernel,
                         cudaFuncAttributeMaxDynamicSharedMemorySize, SMEM_CONV);
    dim3 grid(HW / MPIX, COUT / NCO, NB);   // 49 x 4 x 64
    bconv_kernel<<<grid, 256, SMEM_CONV>>>(b, out);
}

// round 15
// speedup vs baseline: 1.0420x; 1.0420x over previous
#include <cuda_runtime.h>
#include <math.h>
#include <stdint.h>

#define NB   64
#define CIN  256
#define COUT 256
#define HH   56
#define HW   (HH * HH)         // 3136
#define NWORDS 8
#define TAPS 9
#define KW   (TAPS * NWORDS)   // 72 k-words
#define EPSC 1e-5
#define NSLICE 8

__device__ float        g_scale[CIN];
__device__ float        g_shift[CIN];
__device__ double       g_part[CIN * NSLICE * 2];
__device__ unsigned int g_xbits[(size_t)NB * HW * NWORDS];     // [n][pix][word]
__device__ unsigned int g_wkt[KW * COUT];                      // k-major: [k][co]

// ---------------------------------------------------------------------------
// 1) BN stats stage 1: fp32 per-thread partials, double reduction.
// ---------------------------------------------------------------------------
__global__ void bn_stats1_kernel(const float* __restrict__ x) {
    const int c = blockIdx.x, slice = blockIdx.y, nper = NB / NSLICE;
    float fs = 0.f, fs2 = 0.f;
    for (int n = slice * nper; n < (slice + 1) * nper; ++n) {
        const float4* p = (const float4*)(x + ((size_t)n * CIN + c) * HW);
        for (int i = threadIdx.x; i < HW / 4; i += blockDim.x) {
            float4 v = p[i];
            fs  += v.x + v.y + v.z + v.w;
            fs2 += v.x * v.x + v.y * v.y + v.z * v.z + v.w * v.w;
        }
    }
    double s = (double)fs, s2 = (double)fs2;
    __shared__ double ws[32], ws2[32];
    #pragma unroll
    for (int o = 16; o > 0; o >>= 1) {
        s  += __shfl_down_sync(0xffffffffu, s,  o);
        s2 += __shfl_down_sync(0xffffffffu, s2, o);
    }
    const int warp = threadIdx.x >> 5, lane = threadIdx.x & 31;
    if (lane == 0) { ws[warp] = s; ws2[warp] = s2; }
    __syncthreads();
    if (warp == 0) {
        const int nw = blockDim.x >> 5;
        s  = (lane < nw) ? ws[lane]  : 0.0;
        s2 = (lane < nw) ? ws2[lane] : 0.0;
        #pragma unroll
        for (int o = 16; o > 0; o >>= 1) {
            s  += __shfl_down_sync(0xffffffffu, s,  o);
            s2 += __shfl_down_sync(0xffffffffu, s2, o);
        }
        if (lane == 0) {
            g_part[(c * NSLICE + slice) * 2 + 0] = s;
            g_part[(c * NSLICE + slice) * 2 + 1] = s2;
        }
    }
}

// ---------------------------------------------------------------------------
// 2) FUSED: weight bit-pack (k-major) AND bn stage-2 fold (block 0).
// ---------------------------------------------------------------------------
__global__ void packw_bn2_kernel(const float* __restrict__ w,
                                 const float* __restrict__ gamma,
                                 const float* __restrict__ beta) {
    if (blockIdx.x == 0 && threadIdx.x < CIN) {
        const int c = threadIdx.x;
        double s = 0.0, s2 = 0.0;
        #pragma unroll
        for (int k = 0; k < NSLICE; ++k) {
            s  += g_part[(c * NSLICE + k) * 2 + 0];
            s2 += g_part[(c * NSLICE + k) * 2 + 1];
        }
        const double Nt = (double)NB * (double)HW;
        double mean = s / Nt;
        double var  = s2 / Nt - mean * mean;
        float sc = (float)(1.0 / sqrt(var + EPSC)) * gamma[c];
        g_scale[c] = sc;
        g_shift[c] = beta[c] - (float)mean * sc;
    }
    const int idx = blockIdx.x * blockDim.x + threadIdx.x;   // COUT*72
    if (idx >= COUT * KW) return;
    const int word = idx & 7;
    const int tap  = (idx >> 3) % TAPS;
    const int co   = idx / KW;
    const float* p = w + ((size_t)co * CIN + word * 32) * TAPS + tap;
    unsigned int bits = 0;
    #pragma unroll
    for (int j = 0; j < 32; ++j)
        if (p[(size_t)j * TAPS] > 0.0f) bits |= (1u << j);
    g_wkt[(tap * NWORDS + word) * COUT + co] = bits;
}

// ---------------------------------------------------------------------------
// 3) Binarize + bit-pack activations.
// ---------------------------------------------------------------------------
__global__ void pack_x_kernel(const float* __restrict__ x) {
    const int idx = blockIdx.x * blockDim.x + threadIdx.x;
    if (idx >= NB * NWORDS * HW) return;
    const int s    = idx % HW;
    const int t    = idx / HW;
    const int word = t & 7;
    const int n    = t >> 3;
    const int cbase = word * 32;
    const float* p = x + ((size_t)(n * CIN + cbase)) * HW + s;
    unsigned int bits = 0;
    #pragma unroll
    for (int j = 0; j < 32; ++j) {
        float xh = fmaf(p[(size_t)j * HW], g_scale[cbase + j], g_shift[cbase + j]);
        if (xh > 0.0f) bits |= (1u << j);
    }
    g_xbits[((size_t)n * HW + s) * NWORDS + word] = bits;
}

// ---------------------------------------------------------------------------
// 4) GEMM-tiled XNOR-popcount conv.
//    Block: 64 pixels x 128 c_out, 256 threads, thread tile 4x8.
//    k-words processed in pairs -> acc += popc+popc fuses into IADD3.
// ---------------------------------------------------------------------------
#define MPIX 64
#define NCO  128
#define OFF_XS 0
#define OFF_WS (KW * MPIX)
#define OFF_VM (KW * MPIX + KW * NCO)
#define OFF_NV (OFF_VM + TAPS * MPIX)
#define OFF_SB (OFF_NV + MPIX)
#define SMEM_CONV ((OFF_SB + NCO) * 4)

__global__ void __launch_bounds__(256, 3)
bconv_kernel(const float* __restrict__ bias, float* __restrict__ out) {
    extern __shared__ unsigned int sm[];
    unsigned int* sxs = sm + OFF_XS;
    unsigned int* sws = sm + OFF_WS;
    unsigned int* svm = sm + OFF_VM;
    int*          snv = (int*)(sm + OFF_NV);
    float*        sb  = (float*)(sm + OFF_SB);

    const int tid = threadIdx.x;
    const int p0  = blockIdx.x * MPIX;
    const int co0 = blockIdx.y * NCO;
    const int n   = blockIdx.z;

    // fill weights (k-major sub-columns), vectorized: KW * (NCO/4) uint4
    {
        const uint4* src = (const uint4*)(g_wkt);
        uint4* dst = (uint4*)sws;
        for (int i = tid; i < KW * (NCO / 4); i += 256) {
            const int k = i >> 5, q = i & 31;
            dst[k * (NCO / 4) + q] = src[(k * COUT + co0) / 4 + q];
        }
    }
    // fill x im2col + validity masks
    const unsigned int* xb = g_xbits + (size_t)n * HW * NWORDS;
    for (int i = tid; i < KW * MPIX; i += 256) {
        const int k = i >> 6, j = i & 63;
        const int tap = k >> 3, word = k & 7;
        const int dh = tap / 3 - 1, dw = tap % 3 - 1;
        const int p = p0 + j;
        const int h = p / HH, w = p % HH;
        const int hh = h + dh, ww = w + dw;
        const bool valid = (hh >= 0) & (hh < HH) & (ww >= 0) & (ww < HH);
        sxs[i] = valid ? xb[((size_t)hh * HH + ww) * NWORDS + word] : 0u;
        if (word == 0) svm[tap * MPIX + j] = valid ? 0xffffffffu : 0u;
    }
    // nvalid per pixel
    if (tid < MPIX) {
        const int p = p0 + tid;
        const int h = p / HH, w = p % HH;
        int nv = 0;
        #pragma unroll
        for (int tap = 0; tap < TAPS; ++tap) {
            const int hh = h + tap / 3 - 1, ww = w + tap % 3 - 1;
            nv += ((hh >= 0) & (hh < HH) & (ww >= 0) & (ww < HH)) ? 1 : 0;
        }
        snv[tid] = nv;
    }
    if (tid < NCO) sb[tid] = bias[co0 + tid];
    __syncthreads();

    const int pj = (tid & 15) * 4;   // 4 pixels
    const int cj = (tid >> 4) * 8;   // 8 c_out

    int acc[4][8];
    #pragma unroll
    for (int i = 0; i < 4; ++i)
        #pragma unroll
        for (int j = 0; j < 8; ++j) acc[i][j] = 0;

    #pragma unroll 1
    for (int tap = 0; tap < TAPS; ++tap) {
        const uint4 vm = *(const uint4*)(svm + tap * MPIX + pj);
        const unsigned int va[4] = {vm.x, vm.y, vm.z, vm.w};
        #pragma unroll
        for (int wd = 0; wd < NWORDS; wd += 2) {
            const int k0 = tap * NWORDS + wd;
            const int k1 = k0 + 1;
            const uint4 x0 = *(const uint4*)(sxs + k0 * MPIX + pj);
            const uint4 x1 = *(const uint4*)(sxs + k1 * MPIX + pj);
            const uint4 wA = *(const uint4*)(sws + k0 * NCO + cj);
            const uint4 wB = *(const uint4*)(sws + k0 * NCO + cj + 4);
            const uint4 wC = *(const uint4*)(sws + k1 * NCO + cj);
            const uint4 wD = *(const uint4*)(sws + k1 * NCO + cj + 4);
            const unsigned int xa0[4] = {x0.x, x0.y, x0.z, x0.w};
            const unsigned int xa1[4] = {x1.x, x1.y, x1.z, x1.w};
            const unsigned int wa0[8] = {wA.x, wA.y, wA.z, wA.w, wB.x, wB.y, wB.z, wB.w};
            const unsigned int wa1[8] = {wC.x, wC.y, wC.z, wC.w, wD.x, wD.y, wD.z, wD.w};
            #pragma unroll
            for (int i = 0; i < 4; ++i) {
                #pragma unroll
                for (int j = 0; j < 8; ++j) {
                    acc[i][j] += __popc((xa0[i] ^ wa0[j]) & va[i])
                               + __popc((xa1[i] ^ wa1[j]) & va[i]);
                }
            }
        }
    }

    // epilogue
    #pragma unroll
    for (int i = 0; i < 4; ++i) {
        const int p = p0 + pj + i;
        const int base = CIN * snv[pj + i];
        float* op = out + (size_t)n * COUT * HW + p;
        #pragma unroll
        for (int j = 0; j < 8; ++j) {
            const int co = cj + j;
            const float y = (float)(base - 2 * acc[i][j]) + sb[co];
            op[(size_t)(co0 + co) * HW] = fmaxf(y, 0.0f);
        }
    }
}

// ---------------------------------------------------------------------------
extern "C" void kernel_launch(void* const* d_in, const int* in_sizes, int n_in,
                              void* d_out, int out_size) {
    const float* x     = (const float*)d_in[0];
    const float* gamma = (const float*)d_in[1];
    const float* beta  = (const float*)d_in[2];
    const float* w     = (const float*)d_in[3];
    const float* b     = (const float*)d_in[4];
    float* out = (float*)d_out;

    dim3 sgrid(CIN, NSLICE);
    bn_stats1_kernel<<<sgrid, 256>>>(x);

    packw_bn2_kernel<<<(COUT * KW + 255) / 256, 256>>>(w, gamma, beta);

    const int pxn = NB * NWORDS * HW;
    pack_x_kernel<<<(pxn + 255) / 256, 256>>>(x);

    cudaFuncSetAttribute(bconv_kernel,
                         cudaFuncAttributeMaxDynamicSharedMemorySize, SMEM_CONV);
    dim3 grid(HW / MPIX, COUT / NCO, NB);   // 49 x 2 x 64
    bconv_kernel<<<grid, 256, SMEM_CONV>>>(b, out);
}